// round 1
// baseline (speedup 1.0000x reference)
#include <cuda_runtime.h>
#include <cuda_bf16.h>
#include <math.h>

// Problem constants
#define D_MODEL 1024
#define NUM_HEADS 16
#define D_K 64
#define BATCH 4
#define SEQ 2048
#define M_TOTAL (BATCH * SEQ)   // 8192

// Scratch (device globals: allocation-free rule)
__device__ float g_Q[M_TOTAL * D_MODEL];
__device__ float g_K[M_TOTAL * D_MODEL];
__device__ float g_V[M_TOTAL * D_MODEL];
__device__ float g_A[M_TOTAL * D_MODEL];

// ---------------------------------------------------------------------------
// GEMM: C[M,N] = A[M,K] * B[N,K]^T   (both row-major, K contiguous)
// 128x128 tile, BK=16, 256 threads, 8x8 microtile per thread.
// ---------------------------------------------------------------------------
#define GBM 128
#define GBN 128
#define GBK 16

__global__ __launch_bounds__(256) void sgemm_nt(
    const float* __restrict__ A, const float* __restrict__ B,
    float* __restrict__ C, int M, int N, int K)
{
    __shared__ float As[GBK][GBM + 4];
    __shared__ float Bs[GBK][GBN + 4];

    const int tid = threadIdx.x;
    const int tx = tid & 15;      // n-dim
    const int ty = tid >> 4;      // m-dim
    const int m0 = blockIdx.y * GBM;
    const int n0 = blockIdx.x * GBN;

    float acc[8][8];
#pragma unroll
    for (int i = 0; i < 8; i++)
#pragma unroll
        for (int j = 0; j < 8; j++) acc[i][j] = 0.0f;

    for (int k0 = 0; k0 < K; k0 += GBK) {
        // Load A tile (128x16) and B tile (128x16), store transposed [k][row]
#pragma unroll
        for (int i = 0; i < 2; i++) {
            int linear = tid + i * 256;        // 0..511 float4 slots
            int row = linear >> 2;             // 0..127
            int c4  = linear & 3;              // 0..3
            float4 va = *(const float4*)&A[(size_t)(m0 + row) * K + k0 + c4 * 4];
            As[c4 * 4 + 0][row] = va.x;
            As[c4 * 4 + 1][row] = va.y;
            As[c4 * 4 + 2][row] = va.z;
            As[c4 * 4 + 3][row] = va.w;
            float4 vb = *(const float4*)&B[(size_t)(n0 + row) * K + k0 + c4 * 4];
            Bs[c4 * 4 + 0][row] = vb.x;
            Bs[c4 * 4 + 1][row] = vb.y;
            Bs[c4 * 4 + 2][row] = vb.z;
            Bs[c4 * 4 + 3][row] = vb.w;
        }
        __syncthreads();

#pragma unroll
        for (int k = 0; k < GBK; k++) {
            float a[8], b[8];
            *(float4*)&a[0] = *(float4*)&As[k][ty * 8];
            *(float4*)&a[4] = *(float4*)&As[k][ty * 8 + 4];
            *(float4*)&b[0] = *(float4*)&Bs[k][tx * 8];
            *(float4*)&b[4] = *(float4*)&Bs[k][tx * 8 + 4];
#pragma unroll
            for (int i = 0; i < 8; i++)
#pragma unroll
                for (int j = 0; j < 8; j++)
                    acc[i][j] += a[i] * b[j];
        }
        __syncthreads();
    }

#pragma unroll
    for (int i = 0; i < 8; i++) {
        size_t m = (size_t)(m0 + ty * 8 + i);
        float4 v0 = make_float4(acc[i][0], acc[i][1], acc[i][2], acc[i][3]);
        float4 v1 = make_float4(acc[i][4], acc[i][5], acc[i][6], acc[i][7]);
        *(float4*)&C[m * N + n0 + tx * 8]     = v0;
        *(float4*)&C[m * N + n0 + tx * 8 + 4] = v1;
    }
}

// ---------------------------------------------------------------------------
// RoPE (interleaved pairs), applied in-place to Q and K.
// Layout: [m = b*SEQ + s][n = h*64 + d], pair p -> cols (2p, 2p+1)
// ---------------------------------------------------------------------------
__global__ void rope_kernel(float* __restrict__ Q, float* __restrict__ K,
                            const int* __restrict__ tp)
{
    int idx = blockIdx.x * blockDim.x + threadIdx.x;
    const int total = M_TOTAL * (D_MODEL / 2);
    if (idx >= total) return;
    int m = idx >> 9;            // / 512 pairs per row
    int p = idx & 511;
    int s = m & (SEQ - 1);
    int i = p & (D_K / 2 - 1);   // pair index within head (0..31)

    float pos = (float)tp[s];
    // freq computed in double, rounded to fp32 (matches jax fp32 tables ~ulp)
    double fr = exp(-((double)(2 * i) / (double)D_K) * log(10000.0));
    float freq = (float)fr;
    float ang = pos * freq;
    float sn, cs;
    sincosf(ang, &sn, &cs);

    size_t off = (size_t)m * D_MODEL + 2 * p;
    float2 q = *(float2*)&Q[off];
    float2 k = *(float2*)&K[off];
    float2 qo, ko;
    qo.x = cs * q.x - sn * q.y;
    qo.y = cs * q.y + sn * q.x;
    ko.x = cs * k.x - sn * k.y;
    ko.y = cs * k.y + sn * k.x;
    *(float2*)&Q[off] = qo;
    *(float2*)&K[off] = ko;
}

// ---------------------------------------------------------------------------
// Causal flash attention, fp32 SIMT.
// Grid: (SEQ/64, BATCH*NUM_HEADS). Block: 256 threads (16x16), 4x4 microtile.
// Tiles: 64 q-rows x 64 k-cols, d_k = 64.
// Smem (dynamic): Qs[64][65], Ks[64][65], Vs[64][65], Ps[64][65]
// ---------------------------------------------------------------------------
#define AS 65
#define ATTN_SMEM (4 * 64 * AS * (int)sizeof(float))

__global__ __launch_bounds__(256) void attn_kernel(
    const float* __restrict__ Q, const float* __restrict__ K,
    const float* __restrict__ V, float* __restrict__ O)
{
    extern __shared__ float sm[];
    float* Qs = sm;
    float* Ks = sm + 64 * AS;
    float* Vs = sm + 2 * 64 * AS;
    float* Ps = sm + 3 * 64 * AS;

    const int tid = threadIdx.x;
    const int tx = tid & 15;     // k-col group
    const int ty = tid >> 4;     // q-row group
    const int qb = blockIdx.x;
    const int bh = blockIdx.y;
    const int b = bh >> 4;
    const int h = bh & 15;

    const size_t base = (size_t)b * SEQ * D_MODEL + (size_t)h * D_K;
    const int q0 = qb * 64;

    // Load Q tile
#pragma unroll
    for (int i = 0; i < 4; i++) {
        int linear = tid + i * 256;   // 0..1023
        int r = linear >> 4;
        int c4 = linear & 15;
        float4 v = *(const float4*)&Q[base + (size_t)(q0 + r) * D_MODEL + c4 * 4];
        Qs[r * AS + c4 * 4 + 0] = v.x;
        Qs[r * AS + c4 * 4 + 1] = v.y;
        Qs[r * AS + c4 * 4 + 2] = v.z;
        Qs[r * AS + c4 * 4 + 3] = v.w;
    }

    const float NEG_INF = __int_as_float(0xff800000);
    float m_i[4], l_i[4], o[4][4];
#pragma unroll
    for (int r = 0; r < 4; r++) {
        m_i[r] = NEG_INF;
        l_i[r] = 0.0f;
#pragma unroll
        for (int c = 0; c < 4; c++) o[r][c] = 0.0f;
    }
    const float scale = 0.125f;   // 1/sqrt(64)

    for (int kb = 0; kb <= qb; kb++) {
        const int k0 = kb * 64;
        // Load K/V tiles
#pragma unroll
        for (int i = 0; i < 4; i++) {
            int linear = tid + i * 256;
            int r = linear >> 4;
            int c4 = linear & 15;
            float4 vk = *(const float4*)&K[base + (size_t)(k0 + r) * D_MODEL + c4 * 4];
            Ks[r * AS + c4 * 4 + 0] = vk.x;
            Ks[r * AS + c4 * 4 + 1] = vk.y;
            Ks[r * AS + c4 * 4 + 2] = vk.z;
            Ks[r * AS + c4 * 4 + 3] = vk.w;
            float4 vv = *(const float4*)&V[base + (size_t)(k0 + r) * D_MODEL + c4 * 4];
            Vs[r * AS + c4 * 4 + 0] = vv.x;
            Vs[r * AS + c4 * 4 + 1] = vv.y;
            Vs[r * AS + c4 * 4 + 2] = vv.z;
            Vs[r * AS + c4 * 4 + 3] = vv.w;
        }
        __syncthreads();

        // S = Q K^T (4x4 per thread)
        float s[4][4];
#pragma unroll
        for (int r = 0; r < 4; r++)
#pragma unroll
            for (int c = 0; c < 4; c++) s[r][c] = 0.0f;

#pragma unroll 8
        for (int d = 0; d < 64; d++) {
            float qv[4], kv[4];
#pragma unroll
            for (int r = 0; r < 4; r++) qv[r] = Qs[(ty * 4 + r) * AS + d];
#pragma unroll
            for (int c = 0; c < 4; c++) kv[c] = Ks[(tx * 4 + c) * AS + d];
#pragma unroll
            for (int r = 0; r < 4; r++)
#pragma unroll
                for (int c = 0; c < 4; c++)
                    s[r][c] += qv[r] * kv[c];
        }

        // Scale + causal mask (only diagonal block can mask)
        if (kb == qb) {
#pragma unroll
            for (int r = 0; r < 4; r++)
#pragma unroll
                for (int c = 0; c < 4; c++) {
                    s[r][c] *= scale;
                    if (k0 + tx * 4 + c > q0 + ty * 4 + r) s[r][c] = NEG_INF;
                }
        } else {
#pragma unroll
            for (int r = 0; r < 4; r++)
#pragma unroll
                for (int c = 0; c < 4; c++) s[r][c] *= scale;
        }

        // Online softmax per q-row (reduce over the 16 tx lanes)
#pragma unroll
        for (int r = 0; r < 4; r++) {
            float rm = s[r][0];
#pragma unroll
            for (int c = 1; c < 4; c++) rm = fmaxf(rm, s[r][c]);
#pragma unroll
            for (int off = 8; off >= 1; off >>= 1)
                rm = fmaxf(rm, __shfl_xor_sync(0xffffffffu, rm, off));
            float mnew = fmaxf(m_i[r], rm);
            float alpha = __expf(m_i[r] - mnew);
            float rs = 0.0f;
#pragma unroll
            for (int c = 0; c < 4; c++) {
                s[r][c] = __expf(s[r][c] - mnew);
                rs += s[r][c];
            }
#pragma unroll
            for (int off = 8; off >= 1; off >>= 1)
                rs += __shfl_xor_sync(0xffffffffu, rs, off);
            l_i[r] = l_i[r] * alpha + rs;
            m_i[r] = mnew;
#pragma unroll
            for (int c = 0; c < 4; c++) o[r][c] *= alpha;
        }

        // Write P to smem
#pragma unroll
        for (int r = 0; r < 4; r++)
#pragma unroll
            for (int c = 0; c < 4; c++)
                Ps[(ty * 4 + r) * AS + tx * 4 + c] = s[r][c];
        __syncthreads();

        // O += P @ V
#pragma unroll 8
        for (int j = 0; j < 64; j++) {
            float pv[4], vv[4];
#pragma unroll
            for (int r = 0; r < 4; r++) pv[r] = Ps[(ty * 4 + r) * AS + j];
#pragma unroll
            for (int c = 0; c < 4; c++) vv[c] = Vs[j * AS + tx * 4 + c];
#pragma unroll
            for (int r = 0; r < 4; r++)
#pragma unroll
                for (int c = 0; c < 4; c++)
                    o[r][c] += pv[r] * vv[c];
        }
        __syncthreads();
    }

    // Epilogue: normalize and store (layout [b*S+s][h*64+d])
#pragma unroll
    for (int r = 0; r < 4; r++) {
        float invl = 1.0f / l_i[r];
#pragma unroll
        for (int c = 0; c < 4; c++)
            O[base + (size_t)(q0 + ty * 4 + r) * D_MODEL + tx * 4 + c] = o[r][c] * invl;
    }
}

// ---------------------------------------------------------------------------
// Launch
// ---------------------------------------------------------------------------
extern "C" void kernel_launch(void* const* d_in, const int* in_sizes, int n_in,
                              void* d_out, int out_size)
{
    const float* x  = (const float*)d_in[0];
    const int*   tp = (const int*)d_in[1];
    const float* Wq = (const float*)d_in[2];
    const float* Wk = (const float*)d_in[3];
    const float* Wv = (const float*)d_in[4];
    const float* Wo = (const float*)d_in[5];
    float* out = (float*)d_out;

    float *gQ, *gK, *gV, *gA;
    cudaGetSymbolAddress((void**)&gQ, g_Q);
    cudaGetSymbolAddress((void**)&gK, g_K);
    cudaGetSymbolAddress((void**)&gV, g_V);
    cudaGetSymbolAddress((void**)&gA, g_A);

    dim3 gemm_grid(D_MODEL / GBN, M_TOTAL / GBM);   // (8, 64)

    sgemm_nt<<<gemm_grid, 256>>>(x, Wq, gQ, M_TOTAL, D_MODEL, D_MODEL);
    sgemm_nt<<<gemm_grid, 256>>>(x, Wk, gK, M_TOTAL, D_MODEL, D_MODEL);
    sgemm_nt<<<gemm_grid, 256>>>(x, Wv, gV, M_TOTAL, D_MODEL, D_MODEL);

    int rope_total = M_TOTAL * (D_MODEL / 2);
    rope_kernel<<<(rope_total + 255) / 256, 256>>>(gQ, gK, tp);

    cudaFuncSetAttribute(attn_kernel, cudaFuncAttributeMaxDynamicSharedMemorySize, ATTN_SMEM);
    attn_kernel<<<dim3(SEQ / 64, BATCH * NUM_HEADS), 256, ATTN_SMEM>>>(gQ, gK, gV, gA);

    sgemm_nt<<<gemm_grid, 256>>>(gA, Wo, out, M_TOTAL, D_MODEL, D_MODEL);
}

// round 4
// speedup vs baseline: 1.4510x; 1.4510x over previous
#include <cuda_runtime.h>
#include <cuda_bf16.h>
#include <math.h>
#include <stdint.h>

// Problem constants
#define D_MODEL 1024
#define NUM_HEADS 16
#define D_K 64
#define BATCH 4
#define SEQ 2048
#define M_TOTAL (BATCH * SEQ)   // 8192

// ---------------------------------------------------------------------------
// Scratch (device globals)
// ---------------------------------------------------------------------------
__device__ float g_Q[M_TOTAL * D_MODEL];
__device__ float g_K[M_TOTAL * D_MODEL];
__device__ float g_V[M_TOTAL * D_MODEL];
__device__ float g_A[M_TOTAL * D_MODEL];
__device__ __nv_bfloat16 g_xhi[M_TOTAL * D_MODEL];
__device__ __nv_bfloat16 g_xlo[M_TOTAL * D_MODEL];
__device__ __nv_bfloat16 g_ahi[M_TOTAL * D_MODEL];
__device__ __nv_bfloat16 g_alo[M_TOTAL * D_MODEL];
__device__ __nv_bfloat16 g_whi[4][D_MODEL * D_MODEL];
__device__ __nv_bfloat16 g_wlo[4][D_MODEL * D_MODEL];

// ---------------------------------------------------------------------------
// PTX helpers (baseline ISA: sm_80+ — legal on plain sm_100 target)
// ---------------------------------------------------------------------------
__device__ __forceinline__ uint32_t smem_u32(const void* p) {
    uint32_t a;
    asm("{ .reg .u64 t; cvta.to.shared.u64 t, %1; cvt.u32.u64 %0, t; }" : "=r"(a) : "l"(p));
    return a;
}
__device__ __forceinline__ void cpasync16(uint32_t dst, const void* src) {
    asm volatile("cp.async.ca.shared.global [%0], [%1], 16;" :: "r"(dst), "l"(src));
}
#define CPASYNC_COMMIT() asm volatile("cp.async.commit_group;" ::: "memory")
#define CPASYNC_WAIT1()  asm volatile("cp.async.wait_group 1;" ::: "memory")

__device__ __forceinline__ void ldm_x4(uint32_t* r, uint32_t addr) {
    asm volatile("ldmatrix.sync.aligned.m8n8.x4.shared.b16 {%0,%1,%2,%3}, [%4];"
        : "=r"(r[0]), "=r"(r[1]), "=r"(r[2]), "=r"(r[3]) : "r"(addr));
}
__device__ __forceinline__ void mma_bf16(float* c, const uint32_t* a, const uint32_t* b) {
    asm volatile("mma.sync.aligned.m16n8k16.row.col.f32.bf16.bf16.f32 "
        "{%0,%1,%2,%3}, {%4,%5,%6,%7}, {%8,%9}, {%0,%1,%2,%3};"
        : "+f"(c[0]), "+f"(c[1]), "+f"(c[2]), "+f"(c[3])
        : "r"(a[0]), "r"(a[1]), "r"(a[2]), "r"(a[3]), "r"(b[0]), "r"(b[1]));
}

// ---------------------------------------------------------------------------
// fp32 -> (bf16 hi, bf16 lo) split conversion
// ---------------------------------------------------------------------------
__global__ void cvt_split(const float4* __restrict__ in,
                          ushort4* __restrict__ hi, ushort4* __restrict__ lo, int n4)
{
    int i = blockIdx.x * blockDim.x + threadIdx.x;
    if (i >= n4) return;
    float4 v = in[i];
    __nv_bfloat16 h0 = __float2bfloat16(v.x);
    __nv_bfloat16 h1 = __float2bfloat16(v.y);
    __nv_bfloat16 h2 = __float2bfloat16(v.z);
    __nv_bfloat16 h3 = __float2bfloat16(v.w);
    __nv_bfloat16 l0 = __float2bfloat16(v.x - __bfloat162float(h0));
    __nv_bfloat16 l1 = __float2bfloat16(v.y - __bfloat162float(h1));
    __nv_bfloat16 l2 = __float2bfloat16(v.z - __bfloat162float(h2));
    __nv_bfloat16 l3 = __float2bfloat16(v.w - __bfloat162float(h3));
    ushort4 H, L;
    H.x = __bfloat16_as_ushort(h0); H.y = __bfloat16_as_ushort(h1);
    H.z = __bfloat16_as_ushort(h2); H.w = __bfloat16_as_ushort(h3);
    L.x = __bfloat16_as_ushort(l0); L.y = __bfloat16_as_ushort(l1);
    L.z = __bfloat16_as_ushort(l2); L.w = __bfloat16_as_ushort(l3);
    hi[i] = H; lo[i] = L;
}

// ---------------------------------------------------------------------------
// Tensor-core GEMM via mma.sync: C[M,N] = A[M,K]*B[N,K]^T, fp32 out,
// bf16 hi/lo split inputs (3-term compensated product).
// BM=128, BN=128, BK=32, 256 threads (8 warps, 2x4), warp tile 64x32.
// cp.async double-buffered. Smem rows padded to 80B for conflict-free
// ldmatrix (8 consecutive rows hit 8 distinct 4-bank groups).
// ---------------------------------------------------------------------------
#define GK 1024
#define GN 1024
#define ROWB 80                     // bytes per smem row (32 bf16 = 64B + 16B pad)
#define TILE_B (128 * ROWB)         // 10240 bytes per tile
#define S_AHI 0
#define S_ALO TILE_B
#define S_BHI (2 * TILE_B)
#define S_BLO (3 * TILE_B)
#define STAGE_B (4 * TILE_B)        // 40960
#define GEMM_SMEM (2 * STAGE_B)     // 81920
#define NKT (GK / 32)               // 32 k-tiles

__global__ __launch_bounds__(256, 1) void gemm_mma(
    const __nv_bfloat16* __restrict__ Ahi, const __nv_bfloat16* __restrict__ Alo,
    const __nv_bfloat16* __restrict__ Bhi, const __nv_bfloat16* __restrict__ Blo,
    float* __restrict__ C)
{
    extern __shared__ char smem[];
    const uint32_t sb = smem_u32(smem);
    const int tid = threadIdx.x;
    const int wid = tid >> 5;
    const int lane = tid & 31;
    const int m0 = blockIdx.y * 128;
    const int n0 = blockIdx.x * 128;

    const int warp_m = (wid >> 2) * 64;    // 0 or 64
    const int warp_n = (wid & 3) * 32;     // 0,32,64,96

    float acc[4][4][4];
#pragma unroll
    for (int i = 0; i < 4; i++)
#pragma unroll
        for (int j = 0; j < 4; j++)
#pragma unroll
            for (int k = 0; k < 4; k++) acc[i][j][k] = 0.0f;

    // ldmatrix lane addressing (constant per thread)
    const int l7 = lane & 7;
    const int g  = lane >> 3;
    // A x4: rows m..+7 / +8..15, k0 / k8
    const int a_row = (g & 1) * 8 + l7;
    const int a_byte = (g >> 1) * 16;
    // B x4: rows n..+7 / n+8..+15 (two n8 tiles), k0 / k8
    const int b_row = (g >> 1) * 8 + l7;
    const int b_byte = (g & 1) * 16;

    // ---- stage loader ----
    auto load_stage = [&](int kt, int s) {
        const int kbase = kt * 32;
        const uint32_t st = sb + s * STAGE_B;
#pragma unroll
        for (int i = tid; i < 512; i += 256) {
            int row = i >> 2, c16 = i & 3;
            uint32_t d = (uint32_t)(row * ROWB + c16 * 16);
            size_t ga = (size_t)(m0 + row) * GK + kbase + c16 * 8;
            size_t gb = (size_t)(n0 + row) * GK + kbase + c16 * 8;
            cpasync16(st + S_AHI + d, Ahi + ga);
            cpasync16(st + S_ALO + d, Alo + ga);
            cpasync16(st + S_BHI + d, Bhi + gb);
            cpasync16(st + S_BLO + d, Blo + gb);
        }
    };

    load_stage(0, 0); CPASYNC_COMMIT();
    load_stage(1, 1); CPASYNC_COMMIT();

    for (int kt = 0; kt < NKT; kt++) {
        const int s = kt & 1;
        CPASYNC_WAIT1();
        __syncthreads();

        const uint32_t st = sb + s * STAGE_B;
#pragma unroll
        for (int ks = 0; ks < 2; ks++) {
            const int kb = ks * 32;   // byte offset of k16 step
            uint32_t ah[4][4], al[4][4], bh[2][4], bl[2][4];
#pragma unroll
            for (int mt = 0; mt < 4; mt++) {
                uint32_t off = (uint32_t)((warp_m + mt * 16 + a_row) * ROWB + kb + a_byte);
                ldm_x4(ah[mt], st + S_AHI + off);
                ldm_x4(al[mt], st + S_ALO + off);
            }
#pragma unroll
            for (int bt = 0; bt < 2; bt++) {
                uint32_t off = (uint32_t)((warp_n + bt * 16 + b_row) * ROWB + kb + b_byte);
                ldm_x4(bh[bt], st + S_BHI + off);
                ldm_x4(bl[bt], st + S_BLO + off);
            }
#pragma unroll
            for (int mt = 0; mt < 4; mt++)
#pragma unroll
                for (int nt = 0; nt < 4; nt++) {
                    uint32_t* BH = &bh[nt >> 1][(nt & 1) * 2];
                    uint32_t* BL = &bl[nt >> 1][(nt & 1) * 2];
                    mma_bf16(acc[mt][nt], ah[mt], BH);
                    mma_bf16(acc[mt][nt], ah[mt], BL);
                    mma_bf16(acc[mt][nt], al[mt], BH);
                }
        }
        __syncthreads();
        if (kt + 2 < NKT) load_stage(kt + 2, s);
        CPASYNC_COMMIT();
    }

    // ---- epilogue: direct float2 stores ----
#pragma unroll
    for (int mt = 0; mt < 4; mt++) {
#pragma unroll
        for (int nt = 0; nt < 4; nt++) {
            int r = m0 + warp_m + mt * 16 + (lane >> 2);
            int c = n0 + warp_n + nt * 8 + (lane & 3) * 2;
            float2 v0 = make_float2(acc[mt][nt][0], acc[mt][nt][1]);
            float2 v1 = make_float2(acc[mt][nt][2], acc[mt][nt][3]);
            *(float2*)&C[(size_t)r * GN + c] = v0;
            *(float2*)&C[(size_t)(r + 8) * GN + c] = v1;
        }
    }
}

// ---------------------------------------------------------------------------
// RoPE (interleaved pairs), in-place on Q and K.
// ---------------------------------------------------------------------------
__global__ void rope_kernel(float* __restrict__ Q, float* __restrict__ K,
                            const int* __restrict__ tp)
{
    int idx = blockIdx.x * blockDim.x + threadIdx.x;
    const int total = M_TOTAL * (D_MODEL / 2);
    if (idx >= total) return;
    int m = idx >> 9;
    int p = idx & 511;
    int s = m & (SEQ - 1);
    int i = p & (D_K / 2 - 1);

    float pos = (float)tp[s];
    double fr = exp(-((double)(2 * i) / (double)D_K) * log(10000.0));
    float freq = (float)fr;
    float ang = pos * freq;
    float sn, cs;
    sincosf(ang, &sn, &cs);

    size_t off = (size_t)m * D_MODEL + 2 * p;
    float2 q = *(float2*)&Q[off];
    float2 k = *(float2*)&K[off];
    float2 qo, ko;
    qo.x = cs * q.x - sn * q.y;
    qo.y = cs * q.y + sn * q.x;
    ko.x = cs * k.x - sn * k.y;
    ko.y = cs * k.y + sn * k.x;
    *(float2*)&Q[off] = qo;
    *(float2*)&K[off] = ko;
}

// ---------------------------------------------------------------------------
// Causal flash attention, fp32 SIMT (unchanged).
// ---------------------------------------------------------------------------
#define AS 65
#define ATTN_SMEM (4 * 64 * AS * (int)sizeof(float))

__global__ __launch_bounds__(256) void attn_kernel(
    const float* __restrict__ Q, const float* __restrict__ K,
    const float* __restrict__ V, float* __restrict__ O)
{
    extern __shared__ float sm[];
    float* Qs = sm;
    float* Ks = sm + 64 * AS;
    float* Vs = sm + 2 * 64 * AS;
    float* Ps = sm + 3 * 64 * AS;

    const int tid = threadIdx.x;
    const int tx = tid & 15;
    const int ty = tid >> 4;
    const int qb = blockIdx.x;
    const int bh = blockIdx.y;
    const int b = bh >> 4;
    const int h = bh & 15;

    const size_t base = (size_t)b * SEQ * D_MODEL + (size_t)h * D_K;
    const int q0 = qb * 64;

#pragma unroll
    for (int i = 0; i < 4; i++) {
        int linear = tid + i * 256;
        int r = linear >> 4;
        int c4 = linear & 15;
        float4 v = *(const float4*)&Q[base + (size_t)(q0 + r) * D_MODEL + c4 * 4];
        Qs[r * AS + c4 * 4 + 0] = v.x;
        Qs[r * AS + c4 * 4 + 1] = v.y;
        Qs[r * AS + c4 * 4 + 2] = v.z;
        Qs[r * AS + c4 * 4 + 3] = v.w;
    }

    const float NEG_INF = __int_as_float(0xff800000);
    float m_i[4], l_i[4], o[4][4];
#pragma unroll
    for (int r = 0; r < 4; r++) {
        m_i[r] = NEG_INF;
        l_i[r] = 0.0f;
#pragma unroll
        for (int c = 0; c < 4; c++) o[r][c] = 0.0f;
    }
    const float scale = 0.125f;

    for (int kb = 0; kb <= qb; kb++) {
        const int k0 = kb * 64;
#pragma unroll
        for (int i = 0; i < 4; i++) {
            int linear = tid + i * 256;
            int r = linear >> 4;
            int c4 = linear & 15;
            float4 vk = *(const float4*)&K[base + (size_t)(k0 + r) * D_MODEL + c4 * 4];
            Ks[r * AS + c4 * 4 + 0] = vk.x;
            Ks[r * AS + c4 * 4 + 1] = vk.y;
            Ks[r * AS + c4 * 4 + 2] = vk.z;
            Ks[r * AS + c4 * 4 + 3] = vk.w;
            float4 vv = *(const float4*)&V[base + (size_t)(k0 + r) * D_MODEL + c4 * 4];
            Vs[r * AS + c4 * 4 + 0] = vv.x;
            Vs[r * AS + c4 * 4 + 1] = vv.y;
            Vs[r * AS + c4 * 4 + 2] = vv.z;
            Vs[r * AS + c4 * 4 + 3] = vv.w;
        }
        __syncthreads();

        float s[4][4];
#pragma unroll
        for (int r = 0; r < 4; r++)
#pragma unroll
            for (int c = 0; c < 4; c++) s[r][c] = 0.0f;

#pragma unroll 8
        for (int d = 0; d < 64; d++) {
            float qv[4], kv[4];
#pragma unroll
            for (int r = 0; r < 4; r++) qv[r] = Qs[(ty * 4 + r) * AS + d];
#pragma unroll
            for (int c = 0; c < 4; c++) kv[c] = Ks[(tx * 4 + c) * AS + d];
#pragma unroll
            for (int r = 0; r < 4; r++)
#pragma unroll
                for (int c = 0; c < 4; c++)
                    s[r][c] += qv[r] * kv[c];
        }

        if (kb == qb) {
#pragma unroll
            for (int r = 0; r < 4; r++)
#pragma unroll
                for (int c = 0; c < 4; c++) {
                    s[r][c] *= scale;
                    if (k0 + tx * 4 + c > q0 + ty * 4 + r) s[r][c] = NEG_INF;
                }
        } else {
#pragma unroll
            for (int r = 0; r < 4; r++)
#pragma unroll
                for (int c = 0; c < 4; c++) s[r][c] *= scale;
        }

#pragma unroll
        for (int r = 0; r < 4; r++) {
            float rm = s[r][0];
#pragma unroll
            for (int c = 1; c < 4; c++) rm = fmaxf(rm, s[r][c]);
#pragma unroll
            for (int off = 8; off >= 1; off >>= 1)
                rm = fmaxf(rm, __shfl_xor_sync(0xffffffffu, rm, off));
            float mnew = fmaxf(m_i[r], rm);
            float alpha = __expf(m_i[r] - mnew);
            float rs = 0.0f;
#pragma unroll
            for (int c = 0; c < 4; c++) {
                s[r][c] = __expf(s[r][c] - mnew);
                rs += s[r][c];
            }
#pragma unroll
            for (int off = 8; off >= 1; off >>= 1)
                rs += __shfl_xor_sync(0xffffffffu, rs, off);
            l_i[r] = l_i[r] * alpha + rs;
            m_i[r] = mnew;
#pragma unroll
            for (int c = 0; c < 4; c++) o[r][c] *= alpha;
        }

#pragma unroll
        for (int r = 0; r < 4; r++)
#pragma unroll
            for (int c = 0; c < 4; c++)
                Ps[(ty * 4 + r) * AS + tx * 4 + c] = s[r][c];
        __syncthreads();

#pragma unroll 8
        for (int j = 0; j < 64; j++) {
            float pv[4], vv[4];
#pragma unroll
            for (int r = 0; r < 4; r++) pv[r] = Ps[(ty * 4 + r) * AS + j];
#pragma unroll
            for (int c = 0; c < 4; c++) vv[c] = Vs[j * AS + tx * 4 + c];
#pragma unroll
            for (int r = 0; r < 4; r++)
#pragma unroll
                for (int c = 0; c < 4; c++)
                    o[r][c] += pv[r] * vv[c];
        }
        __syncthreads();
    }

#pragma unroll
    for (int r = 0; r < 4; r++) {
        float invl = 1.0f / l_i[r];
#pragma unroll
        for (int c = 0; c < 4; c++)
            O[base + (size_t)(q0 + ty * 4 + r) * D_MODEL + tx * 4 + c] = o[r][c] * invl;
    }
}

// ---------------------------------------------------------------------------
// Launch
// ---------------------------------------------------------------------------
extern "C" void kernel_launch(void* const* d_in, const int* in_sizes, int n_in,
                              void* d_out, int out_size)
{
    const float* x  = (const float*)d_in[0];
    const int*   tp = (const int*)d_in[1];
    const float* Wq = (const float*)d_in[2];
    const float* Wk = (const float*)d_in[3];
    const float* Wv = (const float*)d_in[4];
    const float* Wo = (const float*)d_in[5];
    float* out = (float*)d_out;

    float *gQ, *gK, *gV, *gA;
    __nv_bfloat16 *xhi, *xlo, *ahi, *alo, *whi, *wlo;
    cudaGetSymbolAddress((void**)&gQ, g_Q);
    cudaGetSymbolAddress((void**)&gK, g_K);
    cudaGetSymbolAddress((void**)&gV, g_V);
    cudaGetSymbolAddress((void**)&gA, g_A);
    cudaGetSymbolAddress((void**)&xhi, g_xhi);
    cudaGetSymbolAddress((void**)&xlo, g_xlo);
    cudaGetSymbolAddress((void**)&ahi, g_ahi);
    cudaGetSymbolAddress((void**)&alo, g_alo);
    cudaGetSymbolAddress((void**)&whi, g_whi);
    cudaGetSymbolAddress((void**)&wlo, g_wlo);

    const int WSZ = D_MODEL * D_MODEL;

    // Split conversions
    {
        int n4 = M_TOTAL * D_MODEL / 4;
        cvt_split<<<(n4 + 255) / 256, 256>>>((const float4*)x, (ushort4*)xhi, (ushort4*)xlo, n4);
        int w4 = WSZ / 4;
        cvt_split<<<(w4 + 255) / 256, 256>>>((const float4*)Wq, (ushort4*)(whi + 0 * WSZ), (ushort4*)(wlo + 0 * WSZ), w4);
        cvt_split<<<(w4 + 255) / 256, 256>>>((const float4*)Wk, (ushort4*)(whi + 1 * WSZ), (ushort4*)(wlo + 1 * WSZ), w4);
        cvt_split<<<(w4 + 255) / 256, 256>>>((const float4*)Wv, (ushort4*)(whi + 2 * WSZ), (ushort4*)(wlo + 2 * WSZ), w4);
        cvt_split<<<(w4 + 255) / 256, 256>>>((const float4*)Wo, (ushort4*)(whi + 3 * WSZ), (ushort4*)(wlo + 3 * WSZ), w4);
    }

    cudaFuncSetAttribute(gemm_mma, cudaFuncAttributeMaxDynamicSharedMemorySize, GEMM_SMEM);
    dim3 ggrid(GN / 128, M_TOTAL / 128);   // (8, 64)

    gemm_mma<<<ggrid, 256, GEMM_SMEM>>>(xhi, xlo, whi + 0 * WSZ, wlo + 0 * WSZ, gQ);
    gemm_mma<<<ggrid, 256, GEMM_SMEM>>>(xhi, xlo, whi + 1 * WSZ, wlo + 1 * WSZ, gK);
    gemm_mma<<<ggrid, 256, GEMM_SMEM>>>(xhi, xlo, whi + 2 * WSZ, wlo + 2 * WSZ, gV);

    int rope_total = M_TOTAL * (D_MODEL / 2);
    rope_kernel<<<(rope_total + 255) / 256, 256>>>(gQ, gK, tp);

    cudaFuncSetAttribute(attn_kernel, cudaFuncAttributeMaxDynamicSharedMemorySize, ATTN_SMEM);
    attn_kernel<<<dim3(SEQ / 64, BATCH * NUM_HEADS), 256, ATTN_SMEM>>>(gQ, gK, gV, gA);

    {
        int n4 = M_TOTAL * D_MODEL / 4;
        cvt_split<<<(n4 + 255) / 256, 256>>>((const float4*)gA, (ushort4*)ahi, (ushort4*)alo, n4);
    }
    gemm_mma<<<ggrid, 256, GEMM_SMEM>>>(ahi, alo, whi + 3 * WSZ, wlo + 3 * WSZ, out);
}

// round 5
// speedup vs baseline: 2.6797x; 1.8468x over previous
#include <cuda_runtime.h>
#include <cuda_bf16.h>
#include <math.h>
#include <stdint.h>

// Problem constants
#define D_MODEL 1024
#define NUM_HEADS 16
#define D_K 64
#define BATCH 4
#define SEQ 2048
#define M_TOTAL (BATCH * SEQ)   // 8192

// ---------------------------------------------------------------------------
// Scratch (device globals)
// ---------------------------------------------------------------------------
__device__ float g_Q[M_TOTAL * D_MODEL];
__device__ float g_K[M_TOTAL * D_MODEL];
__device__ float g_V[M_TOTAL * D_MODEL];
__device__ float g_A[M_TOTAL * D_MODEL];
__device__ __nv_bfloat16 g_xhi[M_TOTAL * D_MODEL];
__device__ __nv_bfloat16 g_xlo[M_TOTAL * D_MODEL];
__device__ __nv_bfloat16 g_ahi[M_TOTAL * D_MODEL];
__device__ __nv_bfloat16 g_alo[M_TOTAL * D_MODEL];
__device__ __nv_bfloat16 g_whi[4][D_MODEL * D_MODEL];
__device__ __nv_bfloat16 g_wlo[4][D_MODEL * D_MODEL];
__device__ __nv_bfloat16 g_qhi[M_TOTAL * D_MODEL];
__device__ __nv_bfloat16 g_qlo[M_TOTAL * D_MODEL];
__device__ __nv_bfloat16 g_khi[M_TOTAL * D_MODEL];
__device__ __nv_bfloat16 g_klo[M_TOTAL * D_MODEL];
__device__ __nv_bfloat16 g_vhi[M_TOTAL * D_MODEL];
__device__ __nv_bfloat16 g_vlo[M_TOTAL * D_MODEL];

// ---------------------------------------------------------------------------
// PTX helpers (baseline ISA sm_80+: legal on plain sm_100 target)
// ---------------------------------------------------------------------------
__device__ __forceinline__ uint32_t smem_u32(const void* p) {
    uint32_t a;
    asm("{ .reg .u64 t; cvta.to.shared.u64 t, %1; cvt.u32.u64 %0, t; }" : "=r"(a) : "l"(p));
    return a;
}
__device__ __forceinline__ void cpasync16(uint32_t dst, const void* src) {
    asm volatile("cp.async.ca.shared.global [%0], [%1], 16;" :: "r"(dst), "l"(src));
}
#define CPASYNC_COMMIT() asm volatile("cp.async.commit_group;" ::: "memory")
#define CPASYNC_WAIT1()  asm volatile("cp.async.wait_group 1;" ::: "memory")

__device__ __forceinline__ void ldm_x4(uint32_t* r, uint32_t addr) {
    asm volatile("ldmatrix.sync.aligned.m8n8.x4.shared.b16 {%0,%1,%2,%3}, [%4];"
        : "=r"(r[0]), "=r"(r[1]), "=r"(r[2]), "=r"(r[3]) : "r"(addr));
}
__device__ __forceinline__ void ldm_x4_t(uint32_t* r, uint32_t addr) {
    asm volatile("ldmatrix.sync.aligned.m8n8.x4.trans.shared.b16 {%0,%1,%2,%3}, [%4];"
        : "=r"(r[0]), "=r"(r[1]), "=r"(r[2]), "=r"(r[3]) : "r"(addr));
}
__device__ __forceinline__ void mma_bf16(float* c, const uint32_t* a, const uint32_t* b) {
    asm volatile("mma.sync.aligned.m16n8k16.row.col.f32.bf16.bf16.f32 "
        "{%0,%1,%2,%3}, {%4,%5,%6,%7}, {%8,%9}, {%0,%1,%2,%3};"
        : "+f"(c[0]), "+f"(c[1]), "+f"(c[2]), "+f"(c[3])
        : "r"(a[0]), "r"(a[1]), "r"(a[2]), "r"(a[3]), "r"(b[0]), "r"(b[1]));
}
// pack two floats -> bf16x2 hi, also produce bf16x2 residual (lo)
__device__ __forceinline__ uint32_t pack_split(float a, float b, uint32_t* lo) {
    __nv_bfloat16 ha = __float2bfloat16(a), hb = __float2bfloat16(b);
    __nv_bfloat16 la = __float2bfloat16(a - __bfloat162float(ha));
    __nv_bfloat16 lb = __float2bfloat16(b - __bfloat162float(hb));
    *lo = ((uint32_t)__bfloat16_as_ushort(lb) << 16) | __bfloat16_as_ushort(la);
    return ((uint32_t)__bfloat16_as_ushort(hb) << 16) | __bfloat16_as_ushort(ha);
}

// ---------------------------------------------------------------------------
// fp32 -> (bf16 hi, bf16 lo) split conversion
// ---------------------------------------------------------------------------
__global__ void cvt_split(const float4* __restrict__ in,
                          ushort4* __restrict__ hi, ushort4* __restrict__ lo, int n4)
{
    int i = blockIdx.x * blockDim.x + threadIdx.x;
    if (i >= n4) return;
    float4 v = in[i];
    __nv_bfloat16 h0 = __float2bfloat16(v.x);
    __nv_bfloat16 h1 = __float2bfloat16(v.y);
    __nv_bfloat16 h2 = __float2bfloat16(v.z);
    __nv_bfloat16 h3 = __float2bfloat16(v.w);
    __nv_bfloat16 l0 = __float2bfloat16(v.x - __bfloat162float(h0));
    __nv_bfloat16 l1 = __float2bfloat16(v.y - __bfloat162float(h1));
    __nv_bfloat16 l2 = __float2bfloat16(v.z - __bfloat162float(h2));
    __nv_bfloat16 l3 = __float2bfloat16(v.w - __bfloat162float(h3));
    ushort4 H, L;
    H.x = __bfloat16_as_ushort(h0); H.y = __bfloat16_as_ushort(h1);
    H.z = __bfloat16_as_ushort(h2); H.w = __bfloat16_as_ushort(h3);
    L.x = __bfloat16_as_ushort(l0); L.y = __bfloat16_as_ushort(l1);
    L.z = __bfloat16_as_ushort(l2); L.w = __bfloat16_as_ushort(l3);
    hi[i] = H; lo[i] = L;
}

// ---------------------------------------------------------------------------
// Tensor-core GEMM via mma.sync (unchanged from round 4, verified).
// ---------------------------------------------------------------------------
#define GK 1024
#define GN 1024
#define ROWB 80
#define TILE_B (128 * ROWB)
#define S_AHI 0
#define S_ALO TILE_B
#define S_BHI (2 * TILE_B)
#define S_BLO (3 * TILE_B)
#define STAGE_B (4 * TILE_B)
#define GEMM_SMEM (2 * STAGE_B)
#define NKT (GK / 32)

__global__ __launch_bounds__(256, 1) void gemm_mma(
    const __nv_bfloat16* __restrict__ Ahi, const __nv_bfloat16* __restrict__ Alo,
    const __nv_bfloat16* __restrict__ Bhi, const __nv_bfloat16* __restrict__ Blo,
    float* __restrict__ C)
{
    extern __shared__ char smem[];
    const uint32_t sb = smem_u32(smem);
    const int tid = threadIdx.x;
    const int wid = tid >> 5;
    const int lane = tid & 31;
    const int m0 = blockIdx.y * 128;
    const int n0 = blockIdx.x * 128;

    const int warp_m = (wid >> 2) * 64;
    const int warp_n = (wid & 3) * 32;

    float acc[4][4][4];
#pragma unroll
    for (int i = 0; i < 4; i++)
#pragma unroll
        for (int j = 0; j < 4; j++)
#pragma unroll
            for (int k = 0; k < 4; k++) acc[i][j][k] = 0.0f;

    const int l7 = lane & 7;
    const int g  = lane >> 3;
    const int a_row = (g & 1) * 8 + l7;
    const int a_byte = (g >> 1) * 16;
    const int b_row = (g >> 1) * 8 + l7;
    const int b_byte = (g & 1) * 16;

    auto load_stage = [&](int kt, int s) {
        const int kbase = kt * 32;
        const uint32_t st = sb + s * STAGE_B;
#pragma unroll
        for (int i = tid; i < 512; i += 256) {
            int row = i >> 2, c16 = i & 3;
            uint32_t d = (uint32_t)(row * ROWB + c16 * 16);
            size_t ga = (size_t)(m0 + row) * GK + kbase + c16 * 8;
            size_t gb = (size_t)(n0 + row) * GK + kbase + c16 * 8;
            cpasync16(st + S_AHI + d, Ahi + ga);
            cpasync16(st + S_ALO + d, Alo + ga);
            cpasync16(st + S_BHI + d, Bhi + gb);
            cpasync16(st + S_BLO + d, Blo + gb);
        }
    };

    load_stage(0, 0); CPASYNC_COMMIT();
    load_stage(1, 1); CPASYNC_COMMIT();

    for (int kt = 0; kt < NKT; kt++) {
        const int s = kt & 1;
        CPASYNC_WAIT1();
        __syncthreads();

        const uint32_t st = sb + s * STAGE_B;
#pragma unroll
        for (int ks = 0; ks < 2; ks++) {
            const int kb = ks * 32;
            uint32_t ah[4][4], al[4][4], bh[2][4], bl[2][4];
#pragma unroll
            for (int mt = 0; mt < 4; mt++) {
                uint32_t off = (uint32_t)((warp_m + mt * 16 + a_row) * ROWB + kb + a_byte);
                ldm_x4(ah[mt], st + S_AHI + off);
                ldm_x4(al[mt], st + S_ALO + off);
            }
#pragma unroll
            for (int bt = 0; bt < 2; bt++) {
                uint32_t off = (uint32_t)((warp_n + bt * 16 + b_row) * ROWB + kb + b_byte);
                ldm_x4(bh[bt], st + S_BHI + off);
                ldm_x4(bl[bt], st + S_BLO + off);
            }
#pragma unroll
            for (int mt = 0; mt < 4; mt++)
#pragma unroll
                for (int nt = 0; nt < 4; nt++) {
                    uint32_t* BH = &bh[nt >> 1][(nt & 1) * 2];
                    uint32_t* BL = &bl[nt >> 1][(nt & 1) * 2];
                    mma_bf16(acc[mt][nt], ah[mt], BH);
                    mma_bf16(acc[mt][nt], ah[mt], BL);
                    mma_bf16(acc[mt][nt], al[mt], BH);
                }
        }
        __syncthreads();
        if (kt + 2 < NKT) load_stage(kt + 2, s);
        CPASYNC_COMMIT();
    }

#pragma unroll
    for (int mt = 0; mt < 4; mt++) {
#pragma unroll
        for (int nt = 0; nt < 4; nt++) {
            int r = m0 + warp_m + mt * 16 + (lane >> 2);
            int c = n0 + warp_n + nt * 8 + (lane & 3) * 2;
            float2 v0 = make_float2(acc[mt][nt][0], acc[mt][nt][1]);
            float2 v1 = make_float2(acc[mt][nt][2], acc[mt][nt][3]);
            *(float2*)&C[(size_t)r * GN + c] = v0;
            *(float2*)&C[(size_t)(r + 8) * GN + c] = v1;
        }
    }
}

// ---------------------------------------------------------------------------
// RoPE fused with hi/lo bf16 split. Reads fp32 Q/K (unrotated), writes
// rotated bf16 hi/lo. Q additionally pre-scaled by 1/sqrt(d_k) = 0.125.
// ---------------------------------------------------------------------------
__global__ void rope_split(const float* __restrict__ Q, const float* __restrict__ K,
                           const int* __restrict__ tp,
                           __nv_bfloat16* __restrict__ qhi, __nv_bfloat16* __restrict__ qlo,
                           __nv_bfloat16* __restrict__ khi, __nv_bfloat16* __restrict__ klo)
{
    int idx = blockIdx.x * blockDim.x + threadIdx.x;
    const int total = M_TOTAL * (D_MODEL / 2);
    if (idx >= total) return;
    int m = idx >> 9;
    int p = idx & 511;
    int s = m & (SEQ - 1);
    int i = p & (D_K / 2 - 1);

    float pos = (float)tp[s];
    double fr = exp(-((double)(2 * i) / (double)D_K) * log(10000.0));
    float ang = pos * (float)fr;
    float sn, cs;
    sincosf(ang, &sn, &cs);

    size_t off = (size_t)m * D_MODEL + 2 * p;
    float2 q = *(const float2*)&Q[off];
    float2 k = *(const float2*)&K[off];
    float qx = (cs * q.x - sn * q.y) * 0.125f;
    float qy = (cs * q.y + sn * q.x) * 0.125f;
    float kx = cs * k.x - sn * k.y;
    float ky = cs * k.y + sn * k.x;

    __nv_bfloat16 qhx = __float2bfloat16(qx), qhy = __float2bfloat16(qy);
    __nv_bfloat16 khx = __float2bfloat16(kx), khy = __float2bfloat16(ky);
    ushort2 v;
    v.x = __bfloat16_as_ushort(qhx); v.y = __bfloat16_as_ushort(qhy);
    *(ushort2*)&qhi[off] = v;
    v.x = __bfloat16_as_ushort(__float2bfloat16(qx - __bfloat162float(qhx)));
    v.y = __bfloat16_as_ushort(__float2bfloat16(qy - __bfloat162float(qhy)));
    *(ushort2*)&qlo[off] = v;
    v.x = __bfloat16_as_ushort(khx); v.y = __bfloat16_as_ushort(khy);
    *(ushort2*)&khi[off] = v;
    v.x = __bfloat16_as_ushort(__float2bfloat16(kx - __bfloat162float(khx)));
    v.y = __bfloat16_as_ushort(__float2bfloat16(ky - __bfloat162float(khy)));
    *(ushort2*)&klo[off] = v;
}

// ---------------------------------------------------------------------------
// Flash attention via mma.sync, bf16 hi/lo 3-term compensated.
// 128 threads (4 warps). CTA tile: 64 q-rows; warp: 16 q-rows. BN=64 keys.
// K/V tiles double-buffered via cp.async. Q A-frags held in registers.
// ---------------------------------------------------------------------------
#define AROWB 144                     // 64 bf16 = 128B + 16B pad (conflict-free)
#define ASQ_HI 0
#define ASQ_LO 9216
#define AST_BASE 18432
#define AST_SIZE 36864
#define AK_HI 0
#define AK_LO 9216
#define AV_HI 18432
#define AV_LO 27648
#define ATTN_SMEM (AST_BASE + 2 * AST_SIZE)   // 92160

__global__ __launch_bounds__(128, 2) void attn_mma(
    const __nv_bfloat16* __restrict__ Qhi, const __nv_bfloat16* __restrict__ Qlo,
    const __nv_bfloat16* __restrict__ Khi, const __nv_bfloat16* __restrict__ Klo,
    const __nv_bfloat16* __restrict__ Vhi, const __nv_bfloat16* __restrict__ Vlo,
    float* __restrict__ O)
{
    extern __shared__ char smem[];
    const uint32_t sb = smem_u32(smem);
    const int tid = threadIdx.x, wid = tid >> 5, lane = tid & 31;
    const int qb = gridDim.x - 1 - blockIdx.x;     // long diagonals first
    const int bh = blockIdx.y, b = bh >> 4, h = bh & 15;
    const size_t base = (size_t)b * SEQ * D_MODEL + (size_t)h * D_K;
    const int q0 = qb * 64, wm = wid * 16;

    const int l7 = lane & 7, g = lane >> 3;
    const int a_row = (g & 1) * 8 + l7, a_byte = (g >> 1) * 16;
    const int b_row = (g >> 1) * 8 + l7, b_byte = (g & 1) * 16;
    const int v_row = ((lane >> 3) & 1) * 8 + l7, v_byte = (lane >> 4) * 16;

    // ---- Q tile + KV stage 0 (group 0), KV stage 1 (group 1) ----
    for (int i = tid; i < 512; i += 128) {
        int r = i >> 3, c = i & 7;
        size_t gq = base + (size_t)(q0 + r) * D_MODEL + c * 8;
        uint32_t d = (uint32_t)(r * AROWB + c * 16);
        cpasync16(sb + ASQ_HI + d, Qhi + gq);
        cpasync16(sb + ASQ_LO + d, Qlo + gq);
    }
    auto load_kv = [&](int kb, int s) {
        uint32_t st = sb + AST_BASE + s * AST_SIZE;
        int k0 = kb * 64;
        for (int i = tid; i < 512; i += 128) {
            int r = i >> 3, c = i & 7;
            size_t gk = base + (size_t)(k0 + r) * D_MODEL + c * 8;
            uint32_t d = (uint32_t)(r * AROWB + c * 16);
            cpasync16(st + AK_HI + d, Khi + gk);
            cpasync16(st + AK_LO + d, Klo + gk);
            cpasync16(st + AV_HI + d, Vhi + gk);
            cpasync16(st + AV_LO + d, Vlo + gk);
        }
    };
    load_kv(0, 0); CPASYNC_COMMIT();
    if (qb >= 1) load_kv(1, 1);
    CPASYNC_COMMIT();

    uint32_t qh[4][4], ql[4][4];
    float oacc[8][4];
#pragma unroll
    for (int dt = 0; dt < 8; dt++)
#pragma unroll
        for (int j = 0; j < 4; j++) oacc[dt][j] = 0.0f;
    float mi0 = -1e30f, mi1 = -1e30f, li0 = 0.0f, li1 = 0.0f;

    for (int kb = 0; kb <= qb; kb++) {
        CPASYNC_WAIT1();
        __syncthreads();

        if (kb == 0) {
#pragma unroll
            for (int ks = 0; ks < 4; ks++) {
                uint32_t off = (uint32_t)((wm + a_row) * AROWB + ks * 32 + a_byte);
                ldm_x4(qh[ks], sb + ASQ_HI + off);
                ldm_x4(ql[ks], sb + ASQ_LO + off);
            }
        }

        const uint32_t st = sb + AST_BASE + (kb & 1) * AST_SIZE;

        // ---- S = Q K^T (3-term) ----
        float s[8][4];
#pragma unroll
        for (int nt = 0; nt < 8; nt++)
#pragma unroll
            for (int j = 0; j < 4; j++) s[nt][j] = 0.0f;

#pragma unroll
        for (int ks = 0; ks < 4; ks++) {
            uint32_t kh[4][4], kl[4][4];
#pragma unroll
            for (int bt = 0; bt < 4; bt++) {
                uint32_t off = (uint32_t)((bt * 16 + b_row) * AROWB + ks * 32 + b_byte);
                ldm_x4(kh[bt], st + AK_HI + off);
                ldm_x4(kl[bt], st + AK_LO + off);
            }
#pragma unroll
            for (int nt = 0; nt < 8; nt++) {
                uint32_t* BH = &kh[nt >> 1][(nt & 1) * 2];
                uint32_t* BL = &kl[nt >> 1][(nt & 1) * 2];
                mma_bf16(s[nt], qh[ks], BH);
                mma_bf16(s[nt], qh[ks], BL);
                mma_bf16(s[nt], ql[ks], BH);
            }
        }

        // ---- causal mask (diagonal tile only) ----
        const int lr0 = wm + (lane >> 2), lr1 = lr0 + 8;
        const int cb = (lane & 3) * 2;
        if (kb == qb) {
#pragma unroll
            for (int nt = 0; nt < 8; nt++) {
                int c0 = nt * 8 + cb;
                if (c0 > lr0)     s[nt][0] = -1e30f;
                if (c0 + 1 > lr0) s[nt][1] = -1e30f;
                if (c0 > lr1)     s[nt][2] = -1e30f;
                if (c0 + 1 > lr1) s[nt][3] = -1e30f;
            }
        }

        // ---- online softmax ----
        float rm0 = -1e30f, rm1 = -1e30f;
#pragma unroll
        for (int nt = 0; nt < 8; nt++) {
            rm0 = fmaxf(rm0, fmaxf(s[nt][0], s[nt][1]));
            rm1 = fmaxf(rm1, fmaxf(s[nt][2], s[nt][3]));
        }
        rm0 = fmaxf(rm0, __shfl_xor_sync(0xffffffffu, rm0, 1));
        rm0 = fmaxf(rm0, __shfl_xor_sync(0xffffffffu, rm0, 2));
        rm1 = fmaxf(rm1, __shfl_xor_sync(0xffffffffu, rm1, 1));
        rm1 = fmaxf(rm1, __shfl_xor_sync(0xffffffffu, rm1, 2));
        float mn0 = fmaxf(mi0, rm0), mn1 = fmaxf(mi1, rm1);
        float al0 = __expf(mi0 - mn0), al1 = __expf(mi1 - mn1);
        float rs0 = 0.0f, rs1 = 0.0f;
#pragma unroll
        for (int nt = 0; nt < 8; nt++) {
            s[nt][0] = __expf(s[nt][0] - mn0);
            s[nt][1] = __expf(s[nt][1] - mn0);
            s[nt][2] = __expf(s[nt][2] - mn1);
            s[nt][3] = __expf(s[nt][3] - mn1);
            rs0 += s[nt][0] + s[nt][1];
            rs1 += s[nt][2] + s[nt][3];
        }
        rs0 += __shfl_xor_sync(0xffffffffu, rs0, 1);
        rs0 += __shfl_xor_sync(0xffffffffu, rs0, 2);
        rs1 += __shfl_xor_sync(0xffffffffu, rs1, 1);
        rs1 += __shfl_xor_sync(0xffffffffu, rs1, 2);
        li0 = li0 * al0 + rs0; li1 = li1 * al1 + rs1;
        mi0 = mn0; mi1 = mn1;
#pragma unroll
        for (int dt = 0; dt < 8; dt++) {
            oacc[dt][0] *= al0; oacc[dt][1] *= al0;
            oacc[dt][2] *= al1; oacc[dt][3] *= al1;
        }

        // ---- O += P V (3-term; P hi/lo built in registers) ----
#pragma unroll
        for (int ks = 0; ks < 4; ks++) {
            uint32_t ph[4], pl[4];
            ph[0] = pack_split(s[2 * ks][0],     s[2 * ks][1],     &pl[0]);
            ph[1] = pack_split(s[2 * ks][2],     s[2 * ks][3],     &pl[1]);
            ph[2] = pack_split(s[2 * ks + 1][0], s[2 * ks + 1][1], &pl[2]);
            ph[3] = pack_split(s[2 * ks + 1][2], s[2 * ks + 1][3], &pl[3]);
            uint32_t vh[4][4], vl[4][4];
#pragma unroll
            for (int dp = 0; dp < 4; dp++) {
                uint32_t off = (uint32_t)((ks * 16 + v_row) * AROWB + dp * 32 + v_byte);
                ldm_x4_t(vh[dp], st + AV_HI + off);
                ldm_x4_t(vl[dp], st + AV_LO + off);
            }
#pragma unroll
            for (int dt = 0; dt < 8; dt++) {
                uint32_t* BH = &vh[dt >> 1][(dt & 1) * 2];
                uint32_t* BL = &vl[dt >> 1][(dt & 1) * 2];
                mma_bf16(oacc[dt], ph, BH);
                mma_bf16(oacc[dt], ph, BL);
                mma_bf16(oacc[dt], pl, BH);
            }
        }

        __syncthreads();
        if (kb + 2 <= qb) load_kv(kb + 2, kb & 1);
        CPASYNC_COMMIT();
    }

    // ---- epilogue ----
    float i0 = 1.0f / li0, i1 = 1.0f / li1;
    int r0 = q0 + wm + (lane >> 2);
    int cb = (lane & 3) * 2;
#pragma unroll
    for (int dt = 0; dt < 8; dt++) {
        float2 v0 = make_float2(oacc[dt][0] * i0, oacc[dt][1] * i0);
        float2 v1 = make_float2(oacc[dt][2] * i1, oacc[dt][3] * i1);
        *(float2*)&O[base + (size_t)r0 * D_MODEL + dt * 8 + cb] = v0;
        *(float2*)&O[base + (size_t)(r0 + 8) * D_MODEL + dt * 8 + cb] = v1;
    }
}

// ---------------------------------------------------------------------------
// Launch
// ---------------------------------------------------------------------------
extern "C" void kernel_launch(void* const* d_in, const int* in_sizes, int n_in,
                              void* d_out, int out_size)
{
    const float* x  = (const float*)d_in[0];
    const int*   tp = (const int*)d_in[1];
    const float* Wq = (const float*)d_in[2];
    const float* Wk = (const float*)d_in[3];
    const float* Wv = (const float*)d_in[4];
    const float* Wo = (const float*)d_in[5];
    float* out = (float*)d_out;

    float *gQ, *gK, *gV, *gA;
    __nv_bfloat16 *xhi, *xlo, *ahi, *alo, *whi, *wlo;
    __nv_bfloat16 *qhi, *qlo, *khi, *klo, *vhi, *vlo;
    cudaGetSymbolAddress((void**)&gQ, g_Q);
    cudaGetSymbolAddress((void**)&gK, g_K);
    cudaGetSymbolAddress((void**)&gV, g_V);
    cudaGetSymbolAddress((void**)&gA, g_A);
    cudaGetSymbolAddress((void**)&xhi, g_xhi);
    cudaGetSymbolAddress((void**)&xlo, g_xlo);
    cudaGetSymbolAddress((void**)&ahi, g_ahi);
    cudaGetSymbolAddress((void**)&alo, g_alo);
    cudaGetSymbolAddress((void**)&whi, g_whi);
    cudaGetSymbolAddress((void**)&wlo, g_wlo);
    cudaGetSymbolAddress((void**)&qhi, g_qhi);
    cudaGetSymbolAddress((void**)&qlo, g_qlo);
    cudaGetSymbolAddress((void**)&khi, g_khi);
    cudaGetSymbolAddress((void**)&klo, g_klo);
    cudaGetSymbolAddress((void**)&vhi, g_vhi);
    cudaGetSymbolAddress((void**)&vlo, g_vlo);

    const int WSZ = D_MODEL * D_MODEL;

    {
        int n4 = M_TOTAL * D_MODEL / 4;
        cvt_split<<<(n4 + 255) / 256, 256>>>((const float4*)x, (ushort4*)xhi, (ushort4*)xlo, n4);
        int w4 = WSZ / 4;
        cvt_split<<<(w4 + 255) / 256, 256>>>((const float4*)Wq, (ushort4*)(whi + 0 * WSZ), (ushort4*)(wlo + 0 * WSZ), w4);
        cvt_split<<<(w4 + 255) / 256, 256>>>((const float4*)Wk, (ushort4*)(whi + 1 * WSZ), (ushort4*)(wlo + 1 * WSZ), w4);
        cvt_split<<<(w4 + 255) / 256, 256>>>((const float4*)Wv, (ushort4*)(whi + 2 * WSZ), (ushort4*)(wlo + 2 * WSZ), w4);
        cvt_split<<<(w4 + 255) / 256, 256>>>((const float4*)Wo, (ushort4*)(whi + 3 * WSZ), (ushort4*)(wlo + 3 * WSZ), w4);
    }

    cudaFuncSetAttribute(gemm_mma, cudaFuncAttributeMaxDynamicSharedMemorySize, GEMM_SMEM);
    dim3 ggrid(GN / 128, M_TOTAL / 128);   // (8, 64)

    gemm_mma<<<ggrid, 256, GEMM_SMEM>>>(xhi, xlo, whi + 0 * WSZ, wlo + 0 * WSZ, gQ);
    gemm_mma<<<ggrid, 256, GEMM_SMEM>>>(xhi, xlo, whi + 1 * WSZ, wlo + 1 * WSZ, gK);
    gemm_mma<<<ggrid, 256, GEMM_SMEM>>>(xhi, xlo, whi + 2 * WSZ, wlo + 2 * WSZ, gV);

    {
        int rope_total = M_TOTAL * (D_MODEL / 2);
        rope_split<<<(rope_total + 255) / 256, 256>>>(gQ, gK, tp, qhi, qlo, khi, klo);
        int n4 = M_TOTAL * D_MODEL / 4;
        cvt_split<<<(n4 + 255) / 256, 256>>>((const float4*)gV, (ushort4*)vhi, (ushort4*)vlo, n4);
    }

    cudaFuncSetAttribute(attn_mma, cudaFuncAttributeMaxDynamicSharedMemorySize, ATTN_SMEM);
    attn_mma<<<dim3(SEQ / 64, BATCH * NUM_HEADS), 128, ATTN_SMEM>>>(qhi, qlo, khi, klo, vhi, vlo, gA);

    {
        int n4 = M_TOTAL * D_MODEL / 4;
        cvt_split<<<(n4 + 255) / 256, 256>>>((const float4*)gA, (ushort4*)ahi, (ushort4*)alo, n4);
    }
    gemm_mma<<<ggrid, 256, GEMM_SMEM>>>(ahi, alo, whi + 3 * WSZ, wlo + 3 * WSZ, out);
}

// round 6
// speedup vs baseline: 3.8981x; 1.4547x over previous
#include <cuda_runtime.h>
#include <cuda_bf16.h>
#include <math.h>
#include <stdint.h>

// Problem constants
#define D_MODEL 1024
#define NUM_HEADS 16
#define D_K 64
#define BATCH 4
#define SEQ 2048
#define M_TOTAL (BATCH * SEQ)   // 8192

// ---------------------------------------------------------------------------
// Scratch (device globals)
// ---------------------------------------------------------------------------
__device__ float g_Q[M_TOTAL * D_MODEL];
__device__ float g_K[M_TOTAL * D_MODEL];
__device__ float g_V[M_TOTAL * D_MODEL];
__device__ float g_A[M_TOTAL * D_MODEL];
__device__ __nv_bfloat16 g_qhi[M_TOTAL * D_MODEL];
__device__ __nv_bfloat16 g_qlo[M_TOTAL * D_MODEL];
__device__ __nv_bfloat16 g_khi[M_TOTAL * D_MODEL];
__device__ __nv_bfloat16 g_klo[M_TOTAL * D_MODEL];
__device__ __nv_bfloat16 g_vhi[M_TOTAL * D_MODEL];
__device__ __nv_bfloat16 g_vlo[M_TOTAL * D_MODEL];
// int8 limbs + scales
__device__ int8_t g_x1[M_TOTAL * D_MODEL];
__device__ int8_t g_x0[M_TOTAL * D_MODEL];
__device__ int8_t g_a1[M_TOTAL * D_MODEL];
__device__ int8_t g_a0[M_TOTAL * D_MODEL];
__device__ int8_t g_w1[4][D_MODEL * D_MODEL];
__device__ int8_t g_w0[4][D_MODEL * D_MODEL];
__device__ float  g_sx[M_TOTAL];
__device__ float  g_sa[M_TOTAL];
__device__ float  g_sw[4][D_MODEL];

// ---------------------------------------------------------------------------
// PTX helpers (baseline ISA sm_80+: legal on plain sm_100 target)
// ---------------------------------------------------------------------------
__device__ __forceinline__ uint32_t smem_u32(const void* p) {
    uint32_t a;
    asm("{ .reg .u64 t; cvta.to.shared.u64 t, %1; cvt.u32.u64 %0, t; }" : "=r"(a) : "l"(p));
    return a;
}
__device__ __forceinline__ void cpasync16(uint32_t dst, const void* src) {
    asm volatile("cp.async.ca.shared.global [%0], [%1], 16;" :: "r"(dst), "l"(src));
}
#define CPASYNC_COMMIT() asm volatile("cp.async.commit_group;" ::: "memory")
#define CPASYNC_WAIT1()  asm volatile("cp.async.wait_group 1;" ::: "memory")

__device__ __forceinline__ void ldm_x4(uint32_t* r, uint32_t addr) {
    asm volatile("ldmatrix.sync.aligned.m8n8.x4.shared.b16 {%0,%1,%2,%3}, [%4];"
        : "=r"(r[0]), "=r"(r[1]), "=r"(r[2]), "=r"(r[3]) : "r"(addr));
}
__device__ __forceinline__ void ldm_x4_t(uint32_t* r, uint32_t addr) {
    asm volatile("ldmatrix.sync.aligned.m8n8.x4.trans.shared.b16 {%0,%1,%2,%3}, [%4];"
        : "=r"(r[0]), "=r"(r[1]), "=r"(r[2]), "=r"(r[3]) : "r"(addr));
}
__device__ __forceinline__ void mma_bf16(float* c, const uint32_t* a, const uint32_t* b) {
    asm volatile("mma.sync.aligned.m16n8k16.row.col.f32.bf16.bf16.f32 "
        "{%0,%1,%2,%3}, {%4,%5,%6,%7}, {%8,%9}, {%0,%1,%2,%3};"
        : "+f"(c[0]), "+f"(c[1]), "+f"(c[2]), "+f"(c[3])
        : "r"(a[0]), "r"(a[1]), "r"(a[2]), "r"(a[3]), "r"(b[0]), "r"(b[1]));
}
__device__ __forceinline__ void mma_s8(int* c, const uint32_t* a, const uint32_t* b) {
    asm volatile("mma.sync.aligned.m16n8k32.row.col.s32.s8.s8.s32 "
        "{%0,%1,%2,%3}, {%4,%5,%6,%7}, {%8,%9}, {%0,%1,%2,%3};"
        : "+r"(c[0]), "+r"(c[1]), "+r"(c[2]), "+r"(c[3])
        : "r"(a[0]), "r"(a[1]), "r"(a[2]), "r"(a[3]), "r"(b[0]), "r"(b[1]));
}
__device__ __forceinline__ uint32_t pack_split(float a, float b, uint32_t* lo) {
    __nv_bfloat16 ha = __float2bfloat16(a), hb = __float2bfloat16(b);
    __nv_bfloat16 la = __float2bfloat16(a - __bfloat162float(ha));
    __nv_bfloat16 lb = __float2bfloat16(b - __bfloat162float(hb));
    *lo = ((uint32_t)__bfloat16_as_ushort(lb) << 16) | __bfloat16_as_ushort(la);
    return ((uint32_t)__bfloat16_as_ushort(hb) << 16) | __bfloat16_as_ushort(ha);
}

// ---------------------------------------------------------------------------
// Per-row int8 2-limb quantization: a = s*(128*A1 + A0), s = rowmax/16256.
// grid = rows, block = 256 (K = 1024, one float4 per thread).
// ---------------------------------------------------------------------------
__global__ __launch_bounds__(256) void quant_rows(
    const float* __restrict__ in, char4* __restrict__ h1, char4* __restrict__ h0,
    float* __restrict__ scale)
{
    __shared__ float wmax[8];
    const int r = blockIdx.x, tid = threadIdx.x;
    float4 v = ((const float4*)(in + (size_t)r * 1024))[tid];
    float m = fmaxf(fmaxf(fabsf(v.x), fabsf(v.y)), fmaxf(fabsf(v.z), fabsf(v.w)));
#pragma unroll
    for (int off = 16; off >= 1; off >>= 1)
        m = fmaxf(m, __shfl_xor_sync(0xffffffffu, m, off));
    if ((tid & 31) == 0) wmax[tid >> 5] = m;
    __syncthreads();
    float mx = wmax[0];
#pragma unroll
    for (int i = 1; i < 8; i++) mx = fmaxf(mx, wmax[i]);
    mx = fmaxf(mx, 1e-30f);
    const float inv = 16256.0f / mx;

    char4 c1, c0;
    {
        float t;
        int a1, a0;
        t = fminf(fmaxf(rintf(v.x * inv), -16256.f), 16256.f);
        a1 = __float2int_rn(t * (1.0f / 128.0f)); a0 = (int)t - (a1 << 7);
        c1.x = (char)a1; c0.x = (char)a0;
        t = fminf(fmaxf(rintf(v.y * inv), -16256.f), 16256.f);
        a1 = __float2int_rn(t * (1.0f / 128.0f)); a0 = (int)t - (a1 << 7);
        c1.y = (char)a1; c0.y = (char)a0;
        t = fminf(fmaxf(rintf(v.z * inv), -16256.f), 16256.f);
        a1 = __float2int_rn(t * (1.0f / 128.0f)); a0 = (int)t - (a1 << 7);
        c1.z = (char)a1; c0.z = (char)a0;
        t = fminf(fmaxf(rintf(v.w * inv), -16256.f), 16256.f);
        a1 = __float2int_rn(t * (1.0f / 128.0f)); a0 = (int)t - (a1 << 7);
        c1.w = (char)a1; c0.w = (char)a0;
    }
    h1[(size_t)r * 256 + tid] = c1;
    h0[(size_t)r * 256 + tid] = c0;
    if (tid == 0) scale[r] = mx * (1.0f / 16256.0f);
}

// ---------------------------------------------------------------------------
// fp32 -> (bf16 hi, bf16 lo) split (V path for attention)
// ---------------------------------------------------------------------------
__global__ void cvt_split(const float4* __restrict__ in,
                          ushort4* __restrict__ hi, ushort4* __restrict__ lo, int n4)
{
    int i = blockIdx.x * blockDim.x + threadIdx.x;
    if (i >= n4) return;
    float4 v = in[i];
    __nv_bfloat16 h0 = __float2bfloat16(v.x);
    __nv_bfloat16 h1 = __float2bfloat16(v.y);
    __nv_bfloat16 h2 = __float2bfloat16(v.z);
    __nv_bfloat16 h3 = __float2bfloat16(v.w);
    ushort4 H, L;
    H.x = __bfloat16_as_ushort(h0); H.y = __bfloat16_as_ushort(h1);
    H.z = __bfloat16_as_ushort(h2); H.w = __bfloat16_as_ushort(h3);
    L.x = __bfloat16_as_ushort(__float2bfloat16(v.x - __bfloat162float(h0)));
    L.y = __bfloat16_as_ushort(__float2bfloat16(v.y - __bfloat162float(h1)));
    L.z = __bfloat16_as_ushort(__float2bfloat16(v.z - __bfloat162float(h2)));
    L.w = __bfloat16_as_ushort(__float2bfloat16(v.w - __bfloat162float(h3)));
    hi[i] = H; lo[i] = L;
}

// ---------------------------------------------------------------------------
// Int8 IMMA GEMM: C[M,N] = sa*sb*(A[M,K] * B[N,K]^T), K = 1024.
// BM=128, BN=128, BK=64 bytes (2 k32 steps), 256 thr, warp tile 64x32.
// 3 IMMA per (mt,nt,k32): hh->acc1, (hi*lo + lo*hi)->acc2 (shared acc, exact).
// ---------------------------------------------------------------------------
#define IROWB 80
#define ITILE (128 * IROWB)          // 10240
#define I_A1 0
#define I_A0 ITILE
#define I_B1 (2 * ITILE)
#define I_B0 (3 * ITILE)
#define ISTG (4 * ITILE)             // 40960
#define ISMEM (2 * ISTG + 1024)      // + scale cache
#define INKT 16                      // 1024 / 64

__global__ __launch_bounds__(256, 1) void gemm_i8(
    const int8_t* __restrict__ A1, const int8_t* __restrict__ A0,
    const int8_t* __restrict__ B1, const int8_t* __restrict__ B0,
    const float* __restrict__ sA, const float* __restrict__ sB,
    float* __restrict__ C)
{
    extern __shared__ char smem[];
    const uint32_t sb = smem_u32(smem);
    const int tid = threadIdx.x, wid = tid >> 5, lane = tid & 31;
    const int m0 = blockIdx.y * 128, n0 = blockIdx.x * 128;
    const int warp_m = (wid >> 2) * 64, warp_n = (wid & 3) * 32;

    float* sAs = (float*)(smem + 2 * ISTG);
    float* sBs = sAs + 128;
    if (tid < 128) sAs[tid] = sA[m0 + tid];
    else           sBs[tid - 128] = sB[n0 + tid - 128];

    int acc1[4][4][4], acc2[4][4][4];
#pragma unroll
    for (int i = 0; i < 4; i++)
#pragma unroll
        for (int j = 0; j < 4; j++)
#pragma unroll
            for (int k = 0; k < 4; k++) { acc1[i][j][k] = 0; acc2[i][j][k] = 0; }

    const int l7 = lane & 7, g = lane >> 3;
    const int a_row = (g & 1) * 8 + l7, a_byte = (g >> 1) * 16;
    const int b_row = (g >> 1) * 8 + l7, b_byte = (g & 1) * 16;

    auto load_stage = [&](int kt, int s) {
        const int kbase = kt * 64;
        const uint32_t st = sb + s * ISTG;
#pragma unroll
        for (int i = tid; i < 512; i += 256) {
            int row = i >> 2, c16 = i & 3;
            uint32_t d = (uint32_t)(row * IROWB + c16 * 16);
            size_t ga = (size_t)(m0 + row) * 1024 + kbase + c16 * 16;
            size_t gb = (size_t)(n0 + row) * 1024 + kbase + c16 * 16;
            cpasync16(st + I_A1 + d, A1 + ga);
            cpasync16(st + I_A0 + d, A0 + ga);
            cpasync16(st + I_B1 + d, B1 + gb);
            cpasync16(st + I_B0 + d, B0 + gb);
        }
    };

    load_stage(0, 0); CPASYNC_COMMIT();
    load_stage(1, 1); CPASYNC_COMMIT();

    for (int kt = 0; kt < INKT; kt++) {
        const int s = kt & 1;
        CPASYNC_WAIT1();
        __syncthreads();

        const uint32_t st = sb + s * ISTG;
#pragma unroll
        for (int ks = 0; ks < 2; ks++) {
            const int kb = ks * 32;     // byte offset of k32 step
            uint32_t a1f[4][4], a0f[4][4], b1f[2][4], b0f[2][4];
#pragma unroll
            for (int mt = 0; mt < 4; mt++) {
                uint32_t off = (uint32_t)((warp_m + mt * 16 + a_row) * IROWB + kb + a_byte);
                ldm_x4(a1f[mt], st + I_A1 + off);
                ldm_x4(a0f[mt], st + I_A0 + off);
            }
#pragma unroll
            for (int bt = 0; bt < 2; bt++) {
                uint32_t off = (uint32_t)((warp_n + bt * 16 + b_row) * IROWB + kb + b_byte);
                ldm_x4(b1f[bt], st + I_B1 + off);
                ldm_x4(b0f[bt], st + I_B0 + off);
            }
#pragma unroll
            for (int mt = 0; mt < 4; mt++)
#pragma unroll
                for (int nt = 0; nt < 4; nt++) {
                    uint32_t* B1p = &b1f[nt >> 1][(nt & 1) * 2];
                    uint32_t* B0p = &b0f[nt >> 1][(nt & 1) * 2];
                    mma_s8(acc1[mt][nt], a1f[mt], B1p);
                    mma_s8(acc2[mt][nt], a1f[mt], B0p);
                    mma_s8(acc2[mt][nt], a0f[mt], B1p);
                }
        }
        __syncthreads();
        if (kt + 2 < INKT) load_stage(kt + 2, s);
        CPASYNC_COMMIT();
    }

    // Epilogue: C = sa*sb*128*(128*acc1 + acc2)
#pragma unroll
    for (int mt = 0; mt < 4; mt++) {
#pragma unroll
        for (int nt = 0; nt < 4; nt++) {
            int r = warp_m + mt * 16 + (lane >> 2);
            int c = warp_n + nt * 8 + (lane & 3) * 2;
            float fr0 = 128.0f * sAs[r],  fr1 = 128.0f * sAs[r + 8];
            float sc0 = sBs[c], sc1 = sBs[c + 1];
            float2 v0, v1;
            v0.x = fr0 * sc0 * fmaf(128.0f, (float)acc1[mt][nt][0], (float)acc2[mt][nt][0]);
            v0.y = fr0 * sc1 * fmaf(128.0f, (float)acc1[mt][nt][1], (float)acc2[mt][nt][1]);
            v1.x = fr1 * sc0 * fmaf(128.0f, (float)acc1[mt][nt][2], (float)acc2[mt][nt][2]);
            v1.y = fr1 * sc1 * fmaf(128.0f, (float)acc1[mt][nt][3], (float)acc2[mt][nt][3]);
            *(float2*)&C[(size_t)(m0 + r) * 1024 + n0 + c] = v0;
            *(float2*)&C[(size_t)(m0 + r + 8) * 1024 + n0 + c] = v1;
        }
    }
}

// ---------------------------------------------------------------------------
// RoPE fused with hi/lo bf16 split. Q pre-scaled by 1/sqrt(d_k).
// ---------------------------------------------------------------------------
__global__ void rope_split(const float* __restrict__ Q, const float* __restrict__ K,
                           const int* __restrict__ tp,
                           __nv_bfloat16* __restrict__ qhi, __nv_bfloat16* __restrict__ qlo,
                           __nv_bfloat16* __restrict__ khi, __nv_bfloat16* __restrict__ klo)
{
    int idx = blockIdx.x * blockDim.x + threadIdx.x;
    const int total = M_TOTAL * (D_MODEL / 2);
    if (idx >= total) return;
    int m = idx >> 9;
    int p = idx & 511;
    int s = m & (SEQ - 1);
    int i = p & (D_K / 2 - 1);

    float pos = (float)tp[s];
    double fr = exp(-((double)(2 * i) / (double)D_K) * log(10000.0));
    float ang = pos * (float)fr;
    float sn, cs;
    sincosf(ang, &sn, &cs);

    size_t off = (size_t)m * D_MODEL + 2 * p;
    float2 q = *(const float2*)&Q[off];
    float2 k = *(const float2*)&K[off];
    float qx = (cs * q.x - sn * q.y) * 0.125f;
    float qy = (cs * q.y + sn * q.x) * 0.125f;
    float kx = cs * k.x - sn * k.y;
    float ky = cs * k.y + sn * k.x;

    __nv_bfloat16 qhx = __float2bfloat16(qx), qhy = __float2bfloat16(qy);
    __nv_bfloat16 khx = __float2bfloat16(kx), khy = __float2bfloat16(ky);
    ushort2 v;
    v.x = __bfloat16_as_ushort(qhx); v.y = __bfloat16_as_ushort(qhy);
    *(ushort2*)&qhi[off] = v;
    v.x = __bfloat16_as_ushort(__float2bfloat16(qx - __bfloat162float(qhx)));
    v.y = __bfloat16_as_ushort(__float2bfloat16(qy - __bfloat162float(qhy)));
    *(ushort2*)&qlo[off] = v;
    v.x = __bfloat16_as_ushort(khx); v.y = __bfloat16_as_ushort(khy);
    *(ushort2*)&khi[off] = v;
    v.x = __bfloat16_as_ushort(__float2bfloat16(kx - __bfloat162float(khx)));
    v.y = __bfloat16_as_ushort(__float2bfloat16(ky - __bfloat162float(khy)));
    *(ushort2*)&klo[off] = v;
}

// ---------------------------------------------------------------------------
// Flash attention via mma.sync, bf16 hi/lo 3-term (verified round 5).
// ---------------------------------------------------------------------------
#define AROWB 144
#define ASQ_HI 0
#define ASQ_LO 9216
#define AST_BASE 18432
#define AST_SIZE 36864
#define AK_HI 0
#define AK_LO 9216
#define AV_HI 18432
#define AV_LO 27648
#define ATTN_SMEM (AST_BASE + 2 * AST_SIZE)   // 92160

__global__ __launch_bounds__(128, 2) void attn_mma(
    const __nv_bfloat16* __restrict__ Qhi, const __nv_bfloat16* __restrict__ Qlo,
    const __nv_bfloat16* __restrict__ Khi, const __nv_bfloat16* __restrict__ Klo,
    const __nv_bfloat16* __restrict__ Vhi, const __nv_bfloat16* __restrict__ Vlo,
    float* __restrict__ O)
{
    extern __shared__ char smem[];
    const uint32_t sb = smem_u32(smem);
    const int tid = threadIdx.x, wid = tid >> 5, lane = tid & 31;
    const int qb = gridDim.x - 1 - blockIdx.x;
    const int bh = blockIdx.y, b = bh >> 4, h = bh & 15;
    const size_t base = (size_t)b * SEQ * D_MODEL + (size_t)h * D_K;
    const int q0 = qb * 64, wm = wid * 16;

    const int l7 = lane & 7, g = lane >> 3;
    const int a_row = (g & 1) * 8 + l7, a_byte = (g >> 1) * 16;
    const int b_row = (g >> 1) * 8 + l7, b_byte = (g & 1) * 16;
    const int v_row = ((lane >> 3) & 1) * 8 + l7, v_byte = (lane >> 4) * 16;

    for (int i = tid; i < 512; i += 128) {
        int r = i >> 3, c = i & 7;
        size_t gq = base + (size_t)(q0 + r) * D_MODEL + c * 8;
        uint32_t d = (uint32_t)(r * AROWB + c * 16);
        cpasync16(sb + ASQ_HI + d, Qhi + gq);
        cpasync16(sb + ASQ_LO + d, Qlo + gq);
    }
    auto load_kv = [&](int kb, int s) {
        uint32_t st = sb + AST_BASE + s * AST_SIZE;
        int k0 = kb * 64;
        for (int i = tid; i < 512; i += 128) {
            int r = i >> 3, c = i & 7;
            size_t gk = base + (size_t)(k0 + r) * D_MODEL + c * 8;
            uint32_t d = (uint32_t)(r * AROWB + c * 16);
            cpasync16(st + AK_HI + d, Khi + gk);
            cpasync16(st + AK_LO + d, Klo + gk);
            cpasync16(st + AV_HI + d, Vhi + gk);
            cpasync16(st + AV_LO + d, Vlo + gk);
        }
    };
    load_kv(0, 0); CPASYNC_COMMIT();
    if (qb >= 1) load_kv(1, 1);
    CPASYNC_COMMIT();

    uint32_t qh[4][4], ql[4][4];
    float oacc[8][4];
#pragma unroll
    for (int dt = 0; dt < 8; dt++)
#pragma unroll
        for (int j = 0; j < 4; j++) oacc[dt][j] = 0.0f;
    float mi0 = -1e30f, mi1 = -1e30f, li0 = 0.0f, li1 = 0.0f;

    for (int kb = 0; kb <= qb; kb++) {
        CPASYNC_WAIT1();
        __syncthreads();

        if (kb == 0) {
#pragma unroll
            for (int ks = 0; ks < 4; ks++) {
                uint32_t off = (uint32_t)((wm + a_row) * AROWB + ks * 32 + a_byte);
                ldm_x4(qh[ks], sb + ASQ_HI + off);
                ldm_x4(ql[ks], sb + ASQ_LO + off);
            }
        }

        const uint32_t st = sb + AST_BASE + (kb & 1) * AST_SIZE;

        float s[8][4];
#pragma unroll
        for (int nt = 0; nt < 8; nt++)
#pragma unroll
            for (int j = 0; j < 4; j++) s[nt][j] = 0.0f;

#pragma unroll
        for (int ks = 0; ks < 4; ks++) {
            uint32_t kh[4][4], kl[4][4];
#pragma unroll
            for (int bt = 0; bt < 4; bt++) {
                uint32_t off = (uint32_t)((bt * 16 + b_row) * AROWB + ks * 32 + b_byte);
                ldm_x4(kh[bt], st + AK_HI + off);
                ldm_x4(kl[bt], st + AK_LO + off);
            }
#pragma unroll
            for (int nt = 0; nt < 8; nt++) {
                uint32_t* BH = &kh[nt >> 1][(nt & 1) * 2];
                uint32_t* BL = &kl[nt >> 1][(nt & 1) * 2];
                mma_bf16(s[nt], qh[ks], BH);
                mma_bf16(s[nt], qh[ks], BL);
                mma_bf16(s[nt], ql[ks], BH);
            }
        }

        const int lr0 = wm + (lane >> 2), lr1 = lr0 + 8;
        const int cbm = (lane & 3) * 2;
        if (kb == qb) {
#pragma unroll
            for (int nt = 0; nt < 8; nt++) {
                int c0 = nt * 8 + cbm;
                if (c0 > lr0)     s[nt][0] = -1e30f;
                if (c0 + 1 > lr0) s[nt][1] = -1e30f;
                if (c0 > lr1)     s[nt][2] = -1e30f;
                if (c0 + 1 > lr1) s[nt][3] = -1e30f;
            }
        }

        float rm0 = -1e30f, rm1 = -1e30f;
#pragma unroll
        for (int nt = 0; nt < 8; nt++) {
            rm0 = fmaxf(rm0, fmaxf(s[nt][0], s[nt][1]));
            rm1 = fmaxf(rm1, fmaxf(s[nt][2], s[nt][3]));
        }
        rm0 = fmaxf(rm0, __shfl_xor_sync(0xffffffffu, rm0, 1));
        rm0 = fmaxf(rm0, __shfl_xor_sync(0xffffffffu, rm0, 2));
        rm1 = fmaxf(rm1, __shfl_xor_sync(0xffffffffu, rm1, 1));
        rm1 = fmaxf(rm1, __shfl_xor_sync(0xffffffffu, rm1, 2));
        float mn0 = fmaxf(mi0, rm0), mn1 = fmaxf(mi1, rm1);
        float al0 = __expf(mi0 - mn0), al1 = __expf(mi1 - mn1);
        float rs0 = 0.0f, rs1 = 0.0f;
#pragma unroll
        for (int nt = 0; nt < 8; nt++) {
            s[nt][0] = __expf(s[nt][0] - mn0);
            s[nt][1] = __expf(s[nt][1] - mn0);
            s[nt][2] = __expf(s[nt][2] - mn1);
            s[nt][3] = __expf(s[nt][3] - mn1);
            rs0 += s[nt][0] + s[nt][1];
            rs1 += s[nt][2] + s[nt][3];
        }
        rs0 += __shfl_xor_sync(0xffffffffu, rs0, 1);
        rs0 += __shfl_xor_sync(0xffffffffu, rs0, 2);
        rs1 += __shfl_xor_sync(0xffffffffu, rs1, 1);
        rs1 += __shfl_xor_sync(0xffffffffu, rs1, 2);
        li0 = li0 * al0 + rs0; li1 = li1 * al1 + rs1;
        mi0 = mn0; mi1 = mn1;
#pragma unroll
        for (int dt = 0; dt < 8; dt++) {
            oacc[dt][0] *= al0; oacc[dt][1] *= al0;
            oacc[dt][2] *= al1; oacc[dt][3] *= al1;
        }

#pragma unroll
        for (int ks = 0; ks < 4; ks++) {
            uint32_t ph[4], pl[4];
            ph[0] = pack_split(s[2 * ks][0],     s[2 * ks][1],     &pl[0]);
            ph[1] = pack_split(s[2 * ks][2],     s[2 * ks][3],     &pl[1]);
            ph[2] = pack_split(s[2 * ks + 1][0], s[2 * ks + 1][1], &pl[2]);
            ph[3] = pack_split(s[2 * ks + 1][2], s[2 * ks + 1][3], &pl[3]);
            uint32_t vh[4][4], vl[4][4];
#pragma unroll
            for (int dp = 0; dp < 4; dp++) {
                uint32_t off = (uint32_t)((ks * 16 + v_row) * AROWB + dp * 32 + v_byte);
                ldm_x4_t(vh[dp], st + AV_HI + off);
                ldm_x4_t(vl[dp], st + AV_LO + off);
            }
#pragma unroll
            for (int dt = 0; dt < 8; dt++) {
                uint32_t* BH = &vh[dt >> 1][(dt & 1) * 2];
                uint32_t* BL = &vl[dt >> 1][(dt & 1) * 2];
                mma_bf16(oacc[dt], ph, BH);
                mma_bf16(oacc[dt], ph, BL);
                mma_bf16(oacc[dt], pl, BH);
            }
        }

        __syncthreads();
        if (kb + 2 <= qb) load_kv(kb + 2, kb & 1);
        CPASYNC_COMMIT();
    }

    float i0 = 1.0f / li0, i1 = 1.0f / li1;
    int r0 = q0 + wm + (lane >> 2);
    int cb = (lane & 3) * 2;
#pragma unroll
    for (int dt = 0; dt < 8; dt++) {
        float2 v0 = make_float2(oacc[dt][0] * i0, oacc[dt][1] * i0);
        float2 v1 = make_float2(oacc[dt][2] * i1, oacc[dt][3] * i1);
        *(float2*)&O[base + (size_t)r0 * D_MODEL + dt * 8 + cb] = v0;
        *(float2*)&O[base + (size_t)(r0 + 8) * D_MODEL + dt * 8 + cb] = v1;
    }
}

// ---------------------------------------------------------------------------
// Launch
// ---------------------------------------------------------------------------
extern "C" void kernel_launch(void* const* d_in, const int* in_sizes, int n_in,
                              void* d_out, int out_size)
{
    const float* x  = (const float*)d_in[0];
    const int*   tp = (const int*)d_in[1];
    const float* W[4] = { (const float*)d_in[2], (const float*)d_in[3],
                          (const float*)d_in[4], (const float*)d_in[5] };
    float* out = (float*)d_out;

    float *gQ, *gK, *gV, *gA, *sx, *sa, *sw;
    __nv_bfloat16 *qhi, *qlo, *khi, *klo, *vhi, *vlo;
    int8_t *x1, *x0, *a1, *a0, *w1, *w0;
    cudaGetSymbolAddress((void**)&gQ, g_Q);
    cudaGetSymbolAddress((void**)&gK, g_K);
    cudaGetSymbolAddress((void**)&gV, g_V);
    cudaGetSymbolAddress((void**)&gA, g_A);
    cudaGetSymbolAddress((void**)&qhi, g_qhi);
    cudaGetSymbolAddress((void**)&qlo, g_qlo);
    cudaGetSymbolAddress((void**)&khi, g_khi);
    cudaGetSymbolAddress((void**)&klo, g_klo);
    cudaGetSymbolAddress((void**)&vhi, g_vhi);
    cudaGetSymbolAddress((void**)&vlo, g_vlo);
    cudaGetSymbolAddress((void**)&x1, g_x1);
    cudaGetSymbolAddress((void**)&x0, g_x0);
    cudaGetSymbolAddress((void**)&a1, g_a1);
    cudaGetSymbolAddress((void**)&a0, g_a0);
    cudaGetSymbolAddress((void**)&w1, g_w1);
    cudaGetSymbolAddress((void**)&w0, g_w0);
    cudaGetSymbolAddress((void**)&sx, g_sx);
    cudaGetSymbolAddress((void**)&sa, g_sa);
    cudaGetSymbolAddress((void**)&sw, g_sw);

    const int WSZ = D_MODEL * D_MODEL;

    // Quantize inputs
    quant_rows<<<M_TOTAL, 256>>>(x, (char4*)x1, (char4*)x0, sx);
    for (int i = 0; i < 4; i++)
        quant_rows<<<D_MODEL, 256>>>(W[i], (char4*)(w1 + (size_t)i * WSZ),
                                     (char4*)(w0 + (size_t)i * WSZ), sw + i * D_MODEL);

    cudaFuncSetAttribute(gemm_i8, cudaFuncAttributeMaxDynamicSharedMemorySize, ISMEM);
    dim3 ggrid(D_MODEL / 128, M_TOTAL / 128);   // (8, 64)

    gemm_i8<<<ggrid, 256, ISMEM>>>(x1, x0, w1 + 0 * WSZ, w0 + 0 * WSZ, sx, sw + 0 * D_MODEL, gQ);
    gemm_i8<<<ggrid, 256, ISMEM>>>(x1, x0, w1 + 1 * WSZ, w0 + 1 * WSZ, sx, sw + 1 * D_MODEL, gK);
    gemm_i8<<<ggrid, 256, ISMEM>>>(x1, x0, w1 + 2 * WSZ, w0 + 2 * WSZ, sx, sw + 2 * D_MODEL, gV);

    {
        int rope_total = M_TOTAL * (D_MODEL / 2);
        rope_split<<<(rope_total + 255) / 256, 256>>>(gQ, gK, tp, qhi, qlo, khi, klo);
        int n4 = M_TOTAL * D_MODEL / 4;
        cvt_split<<<(n4 + 255) / 256, 256>>>((const float4*)gV, (ushort4*)vhi, (ushort4*)vlo, n4);
    }

    cudaFuncSetAttribute(attn_mma, cudaFuncAttributeMaxDynamicSharedMemorySize, ATTN_SMEM);
    attn_mma<<<dim3(SEQ / 64, BATCH * NUM_HEADS), 128, ATTN_SMEM>>>(qhi, qlo, khi, klo, vhi, vlo, gA);

    quant_rows<<<M_TOTAL, 256>>>(gA, (char4*)a1, (char4*)a0, sa);
    gemm_i8<<<ggrid, 256, ISMEM>>>(a1, a0, w1 + 3 * WSZ, w0 + 3 * WSZ, sa, sw + 3 * D_MODEL, out);
}